// round 3
// baseline (speedup 1.0000x reference)
#include <cuda_runtime.h>
#include <cstdint>

// BayesEmbedding: out[0 .. B*S*D) = gather(mu + eps*softplus(rho), idx), out[B*S*D] = KL scalar.
// V=50257, D=512, B=8, S=2048.

#define V_ROWS   50257
#define D_DIM    512
#define NELEM    (50257 * 512)          // 25,731,584
#define N4       (NELEM / 4)            // 6,432,896 float4s
#define BS_TOK   16384                  // B*S
#define EMBED_N  (16384 * 512)          // 8,388,608 output floats before kl

// Scale-mixture prior constants (log_q - log_p simplified; +-0.5*log(2pi) cancels):
//   kl_i = -log(sigma) - 0.5*eps^2 - logaddexp(C1 - b1*w^2, C2 - b2*w^2)
//   C1 = log(0.25) + 1,  b1 = 0.5*e^2
//   C2 = log(0.75) + 7,  b2 = 0.5*e^14
#define KL_C1  (-0.3862943611198906f)
#define KL_B1  (3.694528049465325f)
#define KL_C2  (6.712317927786905f)
#define KL_B2  (601302.1420527976f)

__device__ double g_kl_accum;
__device__ int    g_idx_is_64;

__global__ void init_kl_kernel() { g_kl_accum = 0.0; }

// Detect idx dtype: if idx is really int64 (tokens < 2^31), every odd 32-bit
// word (hi half, little-endian) over the first 16384 words is zero. If idx is
// int32, odd words are tokens — ~impossible for 8192 random tokens in [0,V)
// to all be zero. All reads stay within 64 KB, valid under either layout.
__global__ void detect_idx_kernel(const int* __restrict__ idx32) {
    __shared__ int any_nonzero;
    if (threadIdx.x == 0) any_nonzero = 0;
    __syncthreads();
    int local = 0;
    for (int i = threadIdx.x; i < BS_TOK / 2; i += blockDim.x)
        if (idx32[2 * i + 1] != 0) local = 1;
    if (local) any_nonzero = 1;          // benign race: only ever writes 1
    __syncthreads();
    if (threadIdx.x == 0) g_idx_is_64 = (any_nonzero == 0);
}

__device__ __forceinline__ float softplus_fast(float x) {
    // log1p(exp(x)), stable form; MUFU: 1x EX2, 1x LG2
    return fmaxf(x, 0.0f) + __logf(1.0f + __expf(-fabsf(x)));
}

__device__ __forceinline__ float warp_reduce_sum(float v) {
    #pragma unroll
    for (int o = 16; o > 0; o >>= 1) v += __shfl_down_sync(0xFFFFFFFFu, v, o);
    return v;
}

// Pass 1: stream all V*D weights once, accumulate KL. 8 float4 per thread,
// grid-stride for robustness.
#define P1_ITERS 8
#define P1_TPB   256
#define P1_F4_PER_BLOCK (P1_TPB * P1_ITERS)   // 2048 float4 per block

__global__ __launch_bounds__(P1_TPB) void kl_kernel(
    const float4* __restrict__ mu4,
    const float4* __restrict__ rho4,
    const float4* __restrict__ eps4)
{
    float part = 0.0f;

    for (int base = blockIdx.x * P1_F4_PER_BLOCK + threadIdx.x;
         base < N4;
         base += gridDim.x * P1_F4_PER_BLOCK)
    {
        #pragma unroll
        for (int k = 0; k < P1_ITERS; k++) {
            int i = base + k * P1_TPB;
            if (i < N4) {
                float4 m4 = mu4[i];
                float4 r4 = rho4[i];
                float4 e4 = eps4[i];
                const float* m = reinterpret_cast<const float*>(&m4);
                const float* r = reinterpret_cast<const float*>(&r4);
                const float* e = reinterpret_cast<const float*>(&e4);
                #pragma unroll
                for (int c = 0; c < 4; c++) {
                    float sigma = softplus_fast(r[c]) + 1e-5f;
                    float w     = fmaf(e[c], sigma, m[c]);
                    float w2    = w * w;
                    float u1    = fmaf(-KL_B1, w2, KL_C1);
                    float u2    = fmaf(-KL_B2, w2, KL_C2);
                    float mx    = fmaxf(u1, u2);
                    float d     = fabsf(u1 - u2);
                    float lae   = mx + __logf(1.0f + __expf(-d));   // logaddexp
                    part += -__logf(sigma) - 0.5f * e[c] * e[c] - lae;
                }
            }
        }
    }

    // block reduce
    part = warp_reduce_sum(part);
    __shared__ float warp_part[P1_TPB / 32];
    if ((threadIdx.x & 31) == 0) warp_part[threadIdx.x >> 5] = part;
    __syncthreads();
    if (threadIdx.x < 32) {
        float v = (threadIdx.x < (P1_TPB / 32)) ? warp_part[threadIdx.x] : 0.0f;
        v = warp_reduce_sum(v);
        if (threadIdx.x == 0) atomicAdd(&g_kl_accum, (double)v);
    }
}

// Pass 2: gather. One block of 128 threads per token row; each thread does one
// float4 (row is D=512 floats = 128 float4). Recomputes w from mu/rho/eps
// (3x2KB contiguous row reads, partially L2-resident from pass 1).
__global__ __launch_bounds__(128) void gather_kernel(
    const float4* __restrict__ mu4,
    const float4* __restrict__ rho4,
    const float4* __restrict__ eps4,
    const void* __restrict__ idx_raw,
    float4* __restrict__ out4)
{
    const int tok = blockIdx.x;                 // 0 .. BS_TOK-1
    long long row;
    if (g_idx_is_64) row = ((const long long*)idx_raw)[tok];
    else             row = (long long)((const int*)idx_raw)[tok];
    // clamp: never triggers when dtype detection is right; prevents OOB crash
    row = row < 0 ? 0 : (row >= V_ROWS ? V_ROWS - 1 : row);

    const long long src = row * (D_DIM / 4) + threadIdx.x;

    float4 m4 = mu4[src];
    float4 r4 = rho4[src];
    float4 e4 = eps4[src];
    const float* m = reinterpret_cast<const float*>(&m4);
    const float* r = reinterpret_cast<const float*>(&r4);
    const float* e = reinterpret_cast<const float*>(&e4);

    float4 o4;
    float* o = reinterpret_cast<float*>(&o4);
    #pragma unroll
    for (int c = 0; c < 4; c++) {
        float sigma = softplus_fast(r[c]) + 1e-5f;
        o[c] = fmaf(e[c], sigma, m[c]);
    }
    out4[(long long)tok * (D_DIM / 4) + threadIdx.x] = o4;
}

__global__ void write_kl_kernel(float* __restrict__ out, int out_size) {
    if (out_size > EMBED_N) out[EMBED_N] = (float)g_kl_accum;
}

extern "C" void kernel_launch(void* const* d_in, const int* in_sizes, int n_in,
                              void* d_out, int out_size)
{
    const float4* mu4  = (const float4*)d_in[0];
    const float4* rho4 = (const float4*)d_in[1];
    const float4* eps4 = (const float4*)d_in[2];
    const void*   idx  = d_in[3];
    float* out = (float*)d_out;

    init_kl_kernel<<<1, 1>>>();
    detect_idx_kernel<<<1, 256>>>((const int*)idx);

    int p1_blocks = (N4 + P1_F4_PER_BLOCK - 1) / P1_F4_PER_BLOCK;   // 3142
    kl_kernel<<<p1_blocks, P1_TPB>>>(mu4, rho4, eps4);

    gather_kernel<<<BS_TOK, 128>>>(mu4, rho4, eps4, idx, (float4*)out);

    write_kl_kernel<<<1, 1>>>(out, out_size);
}

// round 4
// speedup vs baseline: 1.2177x; 1.2177x over previous
#include <cuda_runtime.h>
#include <cstdint>

// BayesEmbedding: out[0 .. B*S*D) = gather(mu + eps*softplus(rho), idx), out[B*S*D] = KL.
// V=50257, D=512, B=8, S=2048.
// Strategy: invert idx (row -> token buckets), then ONE fused pass streams
// mu/rho/eps, computes KL, and scatters w rows directly to out. Eliminates
// the 96MB gather re-read of round 3.

#define V_ROWS   50257
#define D_DIM    512
#define ROW_F4   (D_DIM / 4)            // 128 float4 per row
#define BS_TOK   16384                  // B*S
#define EMBED_N  (16384 * 512)          // 8,388,608 output floats before kl

// kl_i = -log(sigma) - 0.5*eps^2 - logaddexp(C1 - b1*w^2, C2 - b2*w^2)
#define KL_C1  (-0.3862943611198906f)   // log(0.25) + 1
#define KL_B1  (3.694528049465325f)     // 0.5*e^2
#define KL_C2  (6.712317927786905f)     // log(0.75) + 7
#define KL_B2  (601302.1420527976f)     // 0.5*e^14

#define BUCKET_CAP 8

__device__ double g_kl_accum;
__device__ int    g_idx_is_64;
__device__ int    g_count[V_ROWS];
__device__ int    g_bucket[V_ROWS * BUCKET_CAP];   // token indices (out positions)
__device__ int    g_overflow[BS_TOK];
__device__ int    g_overflow_cnt;

__device__ __forceinline__ float softplus_fast(float x) {
    return fmaxf(x, 0.0f) + __logf(1.0f + __expf(-fabsf(x)));
}

__device__ __forceinline__ float warp_reduce_sum(float v) {
    #pragma unroll
    for (int o = 16; o > 0; o >>= 1) v += __shfl_down_sync(0xFFFFFFFFu, v, o);
    return v;
}

__device__ __forceinline__ long long clamp_row(long long r) {
    return r < 0 ? 0 : (r >= V_ROWS ? V_ROWS - 1 : r);
}

// ---- Kernel 1: zero counters, detect idx dtype (block 0) -------------------
__global__ void setup_kernel(const int* __restrict__ idx32) {
    int gid = blockIdx.x * blockDim.x + threadIdx.x;
    for (int i = gid; i < V_ROWS; i += gridDim.x * blockDim.x) g_count[i] = 0;
    if (gid == 0) { g_kl_accum = 0.0; g_overflow_cnt = 0; }

    if (blockIdx.x == 0) {
        // int64 tokens < 2^31 => all odd 32-bit words (hi halves, LE) are zero.
        __shared__ int any_nonzero;
        if (threadIdx.x == 0) any_nonzero = 0;
        __syncthreads();
        int local = 0;
        for (int i = threadIdx.x; i < BS_TOK / 2; i += blockDim.x)
            if (idx32[2 * i + 1] != 0) local = 1;
        if (local) any_nonzero = 1;
        __syncthreads();
        if (threadIdx.x == 0) g_idx_is_64 = (any_nonzero == 0);
    }
}

// ---- Kernel 2: invert idx into per-row buckets -----------------------------
__global__ void bucket_fill_kernel(const void* __restrict__ idx_raw) {
    int gid = blockIdx.x * blockDim.x + threadIdx.x;
    const int is64 = g_idx_is_64;
    for (int i = gid; i < BS_TOK; i += gridDim.x * blockDim.x) {
        long long row = is64 ? ((const long long*)idx_raw)[i]
                             : (long long)((const int*)idx_raw)[i];
        int r = (int)clamp_row(row);
        int pos = atomicAdd(&g_count[r], 1);
        if (pos < BUCKET_CAP) g_bucket[r * BUCKET_CAP + pos] = i;
        else {
            int o = atomicAdd(&g_overflow_cnt, 1);
            g_overflow[o] = i;
        }
    }
}

// ---- Kernel 3: fused stream + KL + scatter ---------------------------------
// 256 threads = 2 rows in flight; 4 steps => 8 rows per block.
#define ROWS_PER_BLOCK 8
#define MAIN_TPB       256

__global__ __launch_bounds__(MAIN_TPB) void main_kernel(
    const float4* __restrict__ mu4,
    const float4* __restrict__ rho4,
    const float4* __restrict__ eps4,
    float4* __restrict__ out4)
{
    const int base_row = blockIdx.x * ROWS_PER_BLOCK;
    const int sub = threadIdx.x >> 7;        // 0..1
    const int col = threadIdx.x & 127;       // float4 column within row
    float part = 0.0f;

    #pragma unroll
    for (int s = 0; s < 4; s++) {
        const int row = base_row + s * 2 + sub;
        if (row < V_ROWS) {
            const long long src = (long long)row * ROW_F4 + col;
            float4 m4 = mu4[src];
            float4 r4 = rho4[src];
            float4 e4 = eps4[src];
            const float* m = reinterpret_cast<const float*>(&m4);
            const float* r = reinterpret_cast<const float*>(&r4);
            const float* e = reinterpret_cast<const float*>(&e4);

            float4 w4;
            float* w = reinterpret_cast<float*>(&w4);
            #pragma unroll
            for (int c = 0; c < 4; c++) {
                float sigma = softplus_fast(r[c]) + 1e-5f;
                w[c]        = fmaf(e[c], sigma, m[c]);
                float w2    = w[c] * w[c];
                float u1    = fmaf(-KL_B1, w2, KL_C1);
                float u2    = fmaf(-KL_B2, w2, KL_C2);
                float mx    = fmaxf(u1, u2);
                float d     = fabsf(u1 - u2);
                float lae   = mx + __logf(1.0f + __expf(-d));
                part += -__logf(sigma) - 0.5f * e[c] * e[c] - lae;
            }

            int cnt = g_count[row];
            if (cnt > BUCKET_CAP) cnt = BUCKET_CAP;
            for (int j = 0; j < cnt; j++) {
                int tok = g_bucket[row * BUCKET_CAP + j];   // broadcast read
                out4[(long long)tok * ROW_F4 + col] = w4;   // coalesced
            }
        }
    }

    part = warp_reduce_sum(part);
    __shared__ float warp_part[MAIN_TPB / 32];
    if ((threadIdx.x & 31) == 0) warp_part[threadIdx.x >> 5] = part;
    __syncthreads();
    if (threadIdx.x < 32) {
        float v = (threadIdx.x < (MAIN_TPB / 32)) ? warp_part[threadIdx.x] : 0.0f;
        v = warp_reduce_sum(v);
        if (threadIdx.x == 0) atomicAdd(&g_kl_accum, (double)v);
    }
}

// ---- Kernel 4: overflow gather (expected empty) + KL write -----------------
__global__ __launch_bounds__(128) void tail_kernel(
    const float4* __restrict__ mu4,
    const float4* __restrict__ rho4,
    const float4* __restrict__ eps4,
    const void* __restrict__ idx_raw,
    float* __restrict__ out, int out_size)
{
    const int n_ovf = g_overflow_cnt;
    const int is64 = g_idx_is_64;
    float4* out4 = reinterpret_cast<float4*>(out);

    for (int e = 0; e < n_ovf; e++) {
        int i = g_overflow[e];
        long long row = is64 ? ((const long long*)idx_raw)[i]
                             : (long long)((const int*)idx_raw)[i];
        row = clamp_row(row);
        const long long src = row * ROW_F4 + threadIdx.x;
        float4 m4 = mu4[src];
        float4 r4 = rho4[src];
        float4 e4 = eps4[src];
        const float* m = reinterpret_cast<const float*>(&m4);
        const float* r = reinterpret_cast<const float*>(&r4);
        const float* ep = reinterpret_cast<const float*>(&e4);
        float4 o4;
        float* o = reinterpret_cast<float*>(&o4);
        #pragma unroll
        for (int c = 0; c < 4; c++) {
            float sigma = softplus_fast(r[c]) + 1e-5f;
            o[c] = fmaf(ep[c], sigma, m[c]);
        }
        out4[(long long)i * ROW_F4 + threadIdx.x] = o4;
    }

    if (threadIdx.x == 0 && out_size > EMBED_N) out[EMBED_N] = (float)g_kl_accum;
}

extern "C" void kernel_launch(void* const* d_in, const int* in_sizes, int n_in,
                              void* d_out, int out_size)
{
    const float4* mu4  = (const float4*)d_in[0];
    const float4* rho4 = (const float4*)d_in[1];
    const float4* eps4 = (const float4*)d_in[2];
    const void*   idx  = d_in[3];
    float* out = (float*)d_out;

    setup_kernel<<<64, 256>>>((const int*)idx);
    bucket_fill_kernel<<<64, 256>>>(idx);

    int main_blocks = (V_ROWS + ROWS_PER_BLOCK - 1) / ROWS_PER_BLOCK;   // 6283
    main_kernel<<<main_blocks, MAIN_TPB>>>(mu4, rho4, eps4, (float4*)out);

    tail_kernel<<<1, 128>>>(mu4, rho4, eps4, idx, out, out_size);
}